// round 1
// baseline (speedup 1.0000x reference)
#include <cuda_runtime.h>
#include <math.h>

#define BN 8
#define C 256
#define HH 64
#define WW 64
#define HWn 4096
#define KT 9

// ---------------- scratch (device globals: allocation-free) ----------------
__device__ float g_y1[BN*C*HWn];                 // conv1 raw -> (in-place) bn+relu = out1
__device__ float g_d2[BN*C*HWn];                 // deformable conv raw
__device__ float g_res[BN*C*HWn];                // 1x1 shortcut raw
__device__ float g_off[BN*18*HWn];               // offsets
__device__ float g_mask[BN*9*HWn];               // 2*sigmoid modulation
__device__ float g_col[(size_t)BN*C*KT*HWn];     // im2col of sampled values (302 MB)
__device__ float g_stats[6*256];                 // 3x (mean[256], rstd[256])

// ---------------- conv 3x3, 256->256, tile 16x16 px, 32 co / block ----------
__global__ __launch_bounds__(256) void conv3x3_main(
    const float* __restrict__ x, const float* __restrict__ wgt,
    const float* __restrict__ bias, float* __restrict__ y)
{
    __shared__ float xs[8][18][20];   // ci-chunk of padded input tile (pitch 20: conflict-free)
    __shared__ float ws[32][8][9];

    const int tile = blockIdx.x;            // 16 tiles of 16x16
    const int co0  = blockIdx.y * 32;
    const int b    = blockIdx.z;
    const int th0  = (tile >> 2) * 16;
    const int tw0  = (tile & 3) * 16;
    const int tid  = threadIdx.x;
    const int pg   = tid & 63;               // pixel group
    const int cg   = tid >> 6;               // co group (8 co each)
    const int ph   = pg >> 2;                // local row 0..15
    const int pl   = pg & 3;                 // pixel lane: owns cols pl, pl+4, pl+8, pl+12

    float acc[8][4];
    #pragma unroll
    for (int i = 0; i < 8; i++)
        #pragma unroll
        for (int j = 0; j < 4; j++) acc[i][j] = 0.f;

    for (int c0 = 0; c0 < C; c0 += 8) {
        for (int i = tid; i < 8*18*18; i += 256) {
            int ci = i / 324; int r = i - ci*324; int yy = r / 18; int xx = r - yy*18;
            int gy = th0 + yy - 1, gx = tw0 + xx - 1;
            float v = 0.f;
            if (gy >= 0 && gy < HH && gx >= 0 && gx < WW)
                v = x[((b*C + c0+ci)*HH + gy)*WW + gx];
            xs[ci][yy][xx] = v;
        }
        for (int i = tid; i < 32*8*9; i += 256) {
            int co = i / 72; int r = i - co*72; int ci = r / 9; int t = r - ci*9;
            ws[co][ci][t] = wgt[((co0+co)*C + c0+ci)*9 + t];
        }
        __syncthreads();
        for (int ci = 0; ci < 8; ci++) {
            #pragma unroll
            for (int t = 0; t < 9; t++) {
                const int ky = t/3, kx = t%3;
                float xv[4];
                #pragma unroll
                for (int j = 0; j < 4; j++) xv[j] = xs[ci][ph+ky][pl + j*4 + kx];
                #pragma unroll
                for (int i = 0; i < 8; i++) {
                    const float wv = ws[cg*8+i][ci][t];
                    #pragma unroll
                    for (int j = 0; j < 4; j++) acc[i][j] = fmaf(wv, xv[j], acc[i][j]);
                }
            }
        }
        __syncthreads();
    }
    #pragma unroll
    for (int i = 0; i < 8; i++) {
        const int co = co0 + cg*8 + i;
        const float bb = bias[co];
        #pragma unroll
        for (int j = 0; j < 4; j++)
            y[((b*C+co)*HH + th0+ph)*WW + tw0 + pl + j*4] = acc[i][j] + bb;
    }
}

// ---------------- per-channel BN stats: one block per channel ---------------
__global__ __launch_bounds__(256) void bn_stats(const float* __restrict__ src,
                                                float* __restrict__ st)
{
    const int c = blockIdx.x;
    float s = 0.f, s2 = 0.f;
    for (int i = threadIdx.x; i < BN*HWn; i += 256) {
        const int b = i >> 12, pix = i & 4095;
        const float v = src[((b*C + c) << 12) + pix];
        s += v; s2 += v*v;
    }
    __shared__ float sh[512];
    sh[threadIdx.x] = s; sh[256 + threadIdx.x] = s2;
    __syncthreads();
    for (int o = 128; o > 0; o >>= 1) {
        if (threadIdx.x < o) {
            sh[threadIdx.x]       += sh[threadIdx.x + o];
            sh[256 + threadIdx.x] += sh[256 + threadIdx.x + o];
        }
        __syncthreads();
    }
    if (threadIdx.x == 0) {
        const float m   = sh[0]   * (1.f/32768.f);
        const float var = sh[256] * (1.f/32768.f) - m*m;
        st[c]       = m;
        st[256 + c] = rsqrtf(var + 1e-5f);
    }
}

// ---------------- in-place BN + ReLU (for out1) ------------------------------
__global__ __launch_bounds__(256) void bn_relu(float* __restrict__ y,
    const float* __restrict__ st, const float* __restrict__ g, const float* __restrict__ bt)
{
    const int i = blockIdx.x * 256 + threadIdx.x;
    const int c = (i >> 12) & 255;
    const float v = (y[i] - st[c]) * st[256 + c] * g[c] + bt[c];
    y[i] = fmaxf(v, 0.f);
}

// ---------------- fused offset (18ch) + modulation (9ch) 3x3 conv -----------
__global__ __launch_bounds__(256) void conv_offmod(
    const float* __restrict__ src,
    const float* __restrict__ w_off, const float* __restrict__ b_off,
    const float* __restrict__ w_mod, const float* __restrict__ b_mod,
    float* __restrict__ off, float* __restrict__ msk)
{
    __shared__ float xs[8][18][20];
    __shared__ float ws[27][8][9];
    const int tile = blockIdx.x;
    const int b    = blockIdx.z;
    const int th0  = (tile >> 2) * 16;
    const int tw0  = (tile & 3) * 16;
    const int tid  = threadIdx.x;
    const int ph   = tid >> 4;
    const int pw   = tid & 15;

    float acc[27];
    #pragma unroll
    for (int o = 0; o < 27; o++) acc[o] = 0.f;

    for (int c0 = 0; c0 < C; c0 += 8) {
        for (int i = tid; i < 8*18*18; i += 256) {
            int ci = i / 324; int r = i - ci*324; int yy = r / 18; int xx = r - yy*18;
            int gy = th0 + yy - 1, gx = tw0 + xx - 1;
            float v = 0.f;
            if (gy >= 0 && gy < HH && gx >= 0 && gx < WW)
                v = src[((b*C + c0+ci)*HH + gy)*WW + gx];
            xs[ci][yy][xx] = v;
        }
        for (int i = tid; i < 27*72; i += 256) {
            int o = i / 72; int r = i - o*72; int ci = r / 9; int t = r - ci*9;
            ws[o][ci][t] = (o < 18) ? w_off[(o*C + c0+ci)*9 + t]
                                    : w_mod[((o-18)*C + c0+ci)*9 + t];
        }
        __syncthreads();
        for (int ci = 0; ci < 8; ci++) {
            #pragma unroll
            for (int t = 0; t < 9; t++) {
                const float xv = xs[ci][ph + t/3][pw + t%3];
                #pragma unroll
                for (int o = 0; o < 27; o++)
                    acc[o] = fmaf(xv, ws[o][ci][t], acc[o]);
            }
        }
        __syncthreads();
    }
    const int pix = (th0+ph)*WW + tw0+pw;
    #pragma unroll
    for (int o = 0; o < 18; o++)
        off[(b*18 + o)*HWn + pix] = acc[o] + b_off[o];
    #pragma unroll
    for (int o = 0; o < 9; o++) {
        const float v = acc[18+o] + b_mod[o];
        msk[(b*9 + o)*HWn + pix] = 2.f / (1.f + expf(-v));
    }
}

// ---------------- deformable bilinear gather -> im2col ----------------------
__global__ __launch_bounds__(256) void deform_sample(
    const float* __restrict__ src, const float* __restrict__ off,
    const float* __restrict__ msk, float* __restrict__ col)
{
    const int pix = blockIdx.x * 256 + threadIdx.x;
    const int p   = blockIdx.y;
    const int b   = blockIdx.z;
    const int ho  = pix >> 6, wo = pix & 63;

    const float dy = off[(b*18 + 2*p    )*HWn + pix];
    const float dx = off[(b*18 + 2*p + 1)*HWn + pix];
    const float m  = msk[(b*9 + p)*HWn + pix];
    const float py = (float)(ho - 1 + p/3) + dy;
    const float px = (float)(wo - 1 + p%3) + dx;

    const float y0f = floorf(py), x0f = floorf(px);
    const float ly = py - y0f, lx = px - x0f;
    const int y0 = (int)y0f, x0 = (int)x0f;
    const int y1 = y0 + 1,  x1 = x0 + 1;
    float w00 = (1.f-ly)*(1.f-lx), w01 = (1.f-ly)*lx, w10 = ly*(1.f-lx), w11 = ly*lx;
    const bool vy0 = (y0 >= 0) && (y0 < HH), vy1 = (y1 >= 0) && (y1 < HH);
    const bool vx0 = (x0 >= 0) && (x0 < WW), vx1 = (x1 >= 0) && (x1 < WW);
    if (!(vy0 && vx0)) w00 = 0.f;
    if (!(vy0 && vx1)) w01 = 0.f;
    if (!(vy1 && vx0)) w10 = 0.f;
    if (!(vy1 && vx1)) w11 = 0.f;
    const int yc0 = min(max(y0, 0), HH-1), yc1 = min(max(y1, 0), HH-1);
    const int xc0 = min(max(x0, 0), WW-1), xc1 = min(max(x1, 0), WW-1);
    const int o00 = yc0*WW + xc0, o01 = yc0*WW + xc1;
    const int o10 = yc1*WW + xc0, o11 = yc1*WW + xc1;
    w00 *= m; w01 *= m; w10 *= m; w11 *= m;

    const float* bp = src + (size_t)b*C*HWn;
    float* cp = col + ((size_t)b*C*KT + p)*HWn + pix;
    for (int ci = 0; ci < C; ci++) {
        const float* pl = bp + ci*HWn;
        const float v = w00*pl[o00] + w01*pl[o01] + w10*pl[o10] + w11*pl[o11];
        cp[(size_t)ci*KT*HWn] = v;
    }
}

// ---------------- SGEMM: Y[b,co,pix] = bias[co] + sum_k W[co,k]*X[b,k,pix] --
// block tile 64 co x 128 pix, thread tile 4x8
__global__ __launch_bounds__(256) void gemm_ck(
    const float* __restrict__ Wm, const float* __restrict__ Xm,
    const float* __restrict__ bias, float* __restrict__ Ym, int Kdim)
{
    __shared__ float as[16][68];    // [k][co], padded
    __shared__ float bs[16][132];   // [k][pix], padded (16B-aligned rows)
    const int pix0 = blockIdx.x * 128;
    const int co0  = blockIdx.y * 64;
    const int b    = blockIdx.z;
    const int tid  = threadIdx.x;
    const int ct   = tid >> 4;      // co fragment = ct*4
    const int pt   = tid & 15;      // pix fragment = pt*8

    float acc[4][8];
    #pragma unroll
    for (int i = 0; i < 4; i++)
        #pragma unroll
        for (int j = 0; j < 8; j++) acc[i][j] = 0.f;

    const float* Xb = Xm + (size_t)b * Kdim * HWn;
    for (int k0 = 0; k0 < Kdim; k0 += 16) {
        #pragma unroll
        for (int i = 0; i < 4; i++) {
            const int idx = tid + i*256;
            const int kk = idx & 15, co = idx >> 4;
            as[kk][co] = Wm[(size_t)(co0+co)*Kdim + k0 + kk];
        }
        #pragma unroll
        for (int i = 0; i < 2; i++) {
            const int idx = tid + i*256;
            const int kk = idx >> 5, p4 = idx & 31;
            const float4 v = *reinterpret_cast<const float4*>(
                Xb + (size_t)(k0+kk)*HWn + pix0 + p4*4);
            *reinterpret_cast<float4*>(&bs[kk][p4*4]) = v;
        }
        __syncthreads();
        #pragma unroll
        for (int kk = 0; kk < 16; kk++) {
            const float4 av = *reinterpret_cast<const float4*>(&as[kk][ct*4]);
            const float4 b0 = *reinterpret_cast<const float4*>(&bs[kk][pt*8]);
            const float4 b1 = *reinterpret_cast<const float4*>(&bs[kk][pt*8+4]);
            const float a[4]  = {av.x, av.y, av.z, av.w};
            const float bb[8] = {b0.x, b0.y, b0.z, b0.w, b1.x, b1.y, b1.z, b1.w};
            #pragma unroll
            for (int i = 0; i < 4; i++)
                #pragma unroll
                for (int j = 0; j < 8; j++)
                    acc[i][j] = fmaf(a[i], bb[j], acc[i][j]);
        }
        __syncthreads();
    }
    #pragma unroll
    for (int i = 0; i < 4; i++) {
        const int co = co0 + ct*4 + i;
        const float bv = bias[co];
        float* yp = Ym + ((size_t)(b*C + co))*HWn + pix0 + pt*8;
        #pragma unroll
        for (int j = 0; j < 8; j++) yp[j] = acc[i][j] + bv;
    }
}

// ---------------- final: relu( bn2(d2) + bn3(res) ) -------------------------
__global__ __launch_bounds__(256) void final_fuse(
    const float* __restrict__ d2, const float* __restrict__ res,
    const float* __restrict__ st,
    const float* __restrict__ g2, const float* __restrict__ bt2,
    const float* __restrict__ g3, const float* __restrict__ bt3,
    float* __restrict__ out)
{
    const int i = blockIdx.x * 256 + threadIdx.x;
    const int c = (i >> 12) & 255;
    const float a = (d2[i]  - st[512 + c])  * st[768 + c]  * g2[c] + bt2[c];
    const float r = (res[i] - st[1024 + c]) * st[1280 + c] * g3[c] + bt3[c];
    out[i] = fmaxf(a + r, 0.f);
}

// ---------------- launcher ---------------------------------------------------
extern "C" void kernel_launch(void* const* d_in, const int* in_sizes, int n_in,
                              void* d_out, int out_size)
{
    const float* x     = (const float*)d_in[0];
    // d_in[1] = residual (unused by reference)
    const float* w1    = (const float*)d_in[2];
    const float* b1    = (const float*)d_in[3];
    const float* g1    = (const float*)d_in[4];
    const float* bt1   = (const float*)d_in[5];
    const float* w_off = (const float*)d_in[6];
    const float* b_off = (const float*)d_in[7];
    const float* w_mod = (const float*)d_in[8];
    const float* b_mod = (const float*)d_in[9];
    const float* w_d   = (const float*)d_in[10];
    const float* b_d   = (const float*)d_in[11];
    const float* g2    = (const float*)d_in[12];
    const float* bt2   = (const float*)d_in[13];
    const float* w_ds  = (const float*)d_in[14];
    const float* b_ds  = (const float*)d_in[15];
    const float* g3    = (const float*)d_in[16];
    const float* bt3   = (const float*)d_in[17];

    float *y1, *d2, *res, *off, *msk, *col, *st;
    cudaGetSymbolAddress((void**)&y1,  g_y1);
    cudaGetSymbolAddress((void**)&d2,  g_d2);
    cudaGetSymbolAddress((void**)&res, g_res);
    cudaGetSymbolAddress((void**)&off, g_off);
    cudaGetSymbolAddress((void**)&msk, g_mask);
    cudaGetSymbolAddress((void**)&col, g_col);
    cudaGetSymbolAddress((void**)&st,  g_stats);

    // 1) conv1 raw
    conv3x3_main<<<dim3(16, 8, BN), 256>>>(x, w1, b1, y1);
    // 2) BN1 stats + in-place BN+ReLU -> out1
    bn_stats<<<256, 256>>>(y1, st);
    bn_relu<<<BN*C*HWn/256, 256>>>(y1, st, g1, bt1);
    // 3) offsets + modulation
    conv_offmod<<<dim3(16, 1, BN), 256>>>(y1, w_off, b_off, w_mod, b_mod, off, msk);
    // 4) bilinear gather -> im2col
    deform_sample<<<dim3(16, KT, BN), 256>>>(y1, off, msk, col);
    // 5) deformable conv as GEMM (K = 2304)
    gemm_ck<<<dim3(32, 4, BN), 256>>>(w_d, col, b_d, d2, C*KT);
    // 6) 1x1 shortcut as GEMM (K = 256)
    gemm_ck<<<dim3(32, 4, BN), 256>>>(w_ds, x, b_ds, res, C);
    // 7) BN2 / BN3 stats
    bn_stats<<<256, 256>>>(d2,  st + 512);
    bn_stats<<<256, 256>>>(res, st + 1024);
    // 8) fused BN2 + BN3 + add + ReLU
    final_fuse<<<BN*C*HWn/256, 256>>>(d2, res, st, g2, bt2, g3, bt3, (float*)d_out);
}

// round 2
// speedup vs baseline: 2.2867x; 2.2867x over previous
#include <cuda_runtime.h>
#include <math.h>

#define BN 8
#define C 256
#define HH 64
#define WW 64
#define HWn 4096
#define KT 9
#define KFULL (C*KT)   // 2304

// ---------------- scratch (device globals: allocation-free) ----------------
__device__ float g_y1[BN*C*HWn];                 // conv1 raw -> (in-place) bn+relu = out1
__device__ float g_d2[BN*C*HWn];                 // deformable conv raw
__device__ float g_res[BN*C*HWn];                // 1x1 shortcut raw
__device__ float g_off[BN*18*HWn];               // offsets
__device__ float g_mask[BN*9*HWn];               // 2*sigmoid modulation
__device__ float g_col[(size_t)BN*C*KT*HWn];     // im2col of sampled values (302 MB)
__device__ float g_stats[6*256];                 // 3x (mean[256], rstd[256])
__device__ float g_wt1[KFULL*C];                 // w1 transposed  [k][co]
__device__ float g_wtd[KFULL*C];                 // w_d transposed [k][co]
__device__ float g_wts[C*C];                     // w_ds transposed [k][co]
__device__ float g_poff[4*BN*27*HWn];            // offmod partial sums

// ---------------- tf32 mma helpers ------------------------------------------
__device__ __forceinline__ unsigned f2tf(float v) {
    unsigned u; asm("cvt.rna.tf32.f32 %0, %1;" : "=r"(u) : "f"(v)); return u;
}
__device__ __forceinline__ void mma_tf32(float* d, const unsigned* a, const unsigned* b) {
    asm volatile("mma.sync.aligned.m16n8k8.row.col.f32.tf32.tf32.f32 "
        "{%0,%1,%2,%3}, {%4,%5,%6,%7}, {%8,%9}, {%0,%1,%2,%3};"
        : "+f"(d[0]), "+f"(d[1]), "+f"(d[2]), "+f"(d[3])
        : "r"(a[0]), "r"(a[1]), "r"(a[2]), "r"(a[3]), "r"(b[0]), "r"(b[1]));
}

// ---------------- weight transpose: in[CO][K] -> out[K][CO=256] --------------
__global__ __launch_bounds__(256) void transposeW(const float* __restrict__ in,
                                                  float* __restrict__ out, int Kdim)
{
    int idx = blockIdx.x * 256 + threadIdx.x;
    if (idx < Kdim * 256) {
        int co = idx / Kdim;
        int k  = idx - co * Kdim;
        out[k * 256 + co] = in[idx];
    }
}

// ---------------- conv1 3x3 as implicit GEMM on tf32 mma ---------------------
// block: 64 co x 128 pix (2 image rows), 8 warps (2 co x 4 pix)
__global__ __launch_bounds__(256) void conv3x3_mma(
    const float* __restrict__ x, const float* __restrict__ wt,  // wt [2304][256]
    const float* __restrict__ bias, float* __restrict__ y)
{
    __shared__ unsigned ws[72][72];      // [k in ci-chunk][co], pitch 72 (mod32=8)
    __shared__ unsigned xs[8][4][68];    // [ci][4 rows][66 cols pad], tf32 bits

    const int rowb = blockIdx.x;         // 2-row group: rows 2*rowb, 2*rowb+1
    const int pix0 = rowb * 128;
    const int co0  = blockIdx.y * 64;
    const int b    = blockIdx.z;
    const int tid  = threadIdx.x;
    const int warp = tid >> 5, lane = tid & 31;
    const int wm = warp >> 2, wn = warp & 3;
    const int g = lane >> 2, tig = lane & 3;
    const int py  = wn >> 1;
    const int px0 = (wn & 1) * 32 + g;

    float acc[2][4][4];
    #pragma unroll
    for (int m = 0; m < 2; m++)
        #pragma unroll
        for (int n = 0; n < 4; n++)
            #pragma unroll
            for (int q = 0; q < 4; q++) acc[m][n][q] = 0.f;

    for (int ci0 = 0; ci0 < C; ci0 += 8) {
        // stage x tile: 8 ci x 4 rows x 66 cols (zero padded borders)
        for (int i = tid; i < 8*4*66; i += 256) {
            int ci = i / 264; int r = i - ci*264; int ry = r / 66; int j = r - ry*66;
            int gy = 2*rowb - 1 + ry, gx = j - 1;
            float v = 0.f;
            if (gy >= 0 && gy < HH && gx >= 0 && gx < WW)
                v = x[(((size_t)b*C + ci0+ci) << 12) + (gy << 6) + gx];
            xs[ci][ry][j] = f2tf(v);
        }
        // stage weights: k = (ci0+ci)*9+t  ->  72 rows of 64 cos
        #pragma unroll
        for (int i = 0; i < 18; i++) {
            int idx = tid + i*256;
            int co = idx & 63, kk = idx >> 6;
            ws[kk][co] = f2tf(wt[(size_t)(ci0*9 + kk)*256 + co0 + co]);
        }
        __syncthreads();
        #pragma unroll
        for (int s = 0; s < 9; s++) {
            const int kb = s*8;
            unsigned af[2][4];
            #pragma unroll
            for (int m = 0; m < 2; m++) {
                const int cw = wm*32 + m*16;
                af[m][0] = ws[kb+tig  ][cw+g];
                af[m][1] = ws[kb+tig  ][cw+g+8];
                af[m][2] = ws[kb+tig+4][cw+g];
                af[m][3] = ws[kb+tig+4][cw+g+8];
            }
            const int kB0 = kb + tig, kB1 = kb + tig + 4;
            const int ci0l = kB0/9, t0 = kB0 - ci0l*9, ky0 = t0/3, kx0 = t0 - 3*(t0/3);
            const int ci1l = kB1/9, t1 = kB1 - ci1l*9, ky1 = t1/3, kx1 = t1 - 3*(t1/3);
            const unsigned* b0p = &xs[ci0l][py+ky0][px0 + kx0];
            const unsigned* b1p = &xs[ci1l][py+ky1][px0 + kx1];
            unsigned bf[4][2];
            #pragma unroll
            for (int n = 0; n < 4; n++) { bf[n][0] = b0p[n*8]; bf[n][1] = b1p[n*8]; }
            #pragma unroll
            for (int m = 0; m < 2; m++)
                #pragma unroll
                for (int n = 0; n < 4; n++)
                    mma_tf32(acc[m][n], af[m], bf[n]);
        }
        __syncthreads();
    }
    #pragma unroll
    for (int m = 0; m < 2; m++) {
        const int r0 = co0 + wm*32 + m*16 + g;
        const float bv0 = bias[r0], bv1 = bias[r0+8];
        #pragma unroll
        for (int n = 0; n < 4; n++) {
            const int pc = pix0 + wn*32 + n*8 + 2*tig;
            float* y0 = y + (((size_t)b*C + r0)   << 12) + pc;
            float* y1 = y + (((size_t)b*C + r0+8) << 12) + pc;
            y0[0] = acc[m][n][0] + bv0; y0[1] = acc[m][n][1] + bv0;
            y1[0] = acc[m][n][2] + bv1; y1[1] = acc[m][n][3] + bv1;
        }
    }
}

// ---------------- generic tf32 GEMM: Y[b,co,pix] = bias + W[co,k] X[b,k,pix] --
// Wt is k-major [K][256]. block 64co x 128pix, K-chunk 32.
__global__ __launch_bounds__(256) void gemm_tf32(
    const float* __restrict__ Wt, const float* __restrict__ Xm,
    const float* __restrict__ bias, float* __restrict__ Ym, int Kdim)
{
    __shared__ unsigned as[32][72];
    __shared__ unsigned bs[32][136];
    const int pix0 = blockIdx.x * 128;
    const int co0  = blockIdx.y * 64;
    const int b    = blockIdx.z;
    const int tid  = threadIdx.x;
    const int warp = tid >> 5, lane = tid & 31;
    const int wm = warp >> 2, wn = warp & 3;
    const int g = lane >> 2, tig = lane & 3;

    float acc[2][4][4];
    #pragma unroll
    for (int m = 0; m < 2; m++)
        #pragma unroll
        for (int n = 0; n < 4; n++)
            #pragma unroll
            for (int q = 0; q < 4; q++) acc[m][n][q] = 0.f;

    const float* Xb = Xm + (size_t)b * Kdim * HWn;
    for (int k0 = 0; k0 < Kdim; k0 += 32) {
        #pragma unroll
        for (int i = 0; i < 8; i++) {
            int idx = tid + i*256;
            int co = idx & 63, kk = idx >> 6;
            as[kk][co] = f2tf(Wt[(size_t)(k0+kk)*256 + co0 + co]);
        }
        #pragma unroll
        for (int i = 0; i < 4; i++) {
            int idx = tid + i*256;
            int kk = idx >> 5, p4 = idx & 31;
            const float4 v = *reinterpret_cast<const float4*>(
                Xb + (size_t)(k0+kk)*HWn + pix0 + p4*4);
            unsigned* dst = &bs[kk][p4*4];
            dst[0] = f2tf(v.x); dst[1] = f2tf(v.y); dst[2] = f2tf(v.z); dst[3] = f2tf(v.w);
        }
        __syncthreads();
        #pragma unroll
        for (int s = 0; s < 4; s++) {
            const int kb = s*8;
            unsigned af[2][4], bf[4][2];
            #pragma unroll
            for (int m = 0; m < 2; m++) {
                const int cw = wm*32 + m*16;
                af[m][0] = as[kb+tig  ][cw+g];
                af[m][1] = as[kb+tig  ][cw+g+8];
                af[m][2] = as[kb+tig+4][cw+g];
                af[m][3] = as[kb+tig+4][cw+g+8];
            }
            #pragma unroll
            for (int n = 0; n < 4; n++) {
                const int pc = wn*32 + n*8 + g;
                bf[n][0] = bs[kb+tig  ][pc];
                bf[n][1] = bs[kb+tig+4][pc];
            }
            #pragma unroll
            for (int m = 0; m < 2; m++)
                #pragma unroll
                for (int n = 0; n < 4; n++)
                    mma_tf32(acc[m][n], af[m], bf[n]);
        }
        __syncthreads();
    }
    #pragma unroll
    for (int m = 0; m < 2; m++) {
        const int r0 = co0 + wm*32 + m*16 + g;
        const float bv0 = bias[r0], bv1 = bias[r0+8];
        #pragma unroll
        for (int n = 0; n < 4; n++) {
            const int pc = pix0 + wn*32 + n*8 + 2*tig;
            float* y0 = Ym + (((size_t)b*C + r0)   << 12) + pc;
            float* y1 = Ym + (((size_t)b*C + r0+8) << 12) + pc;
            y0[0] = acc[m][n][0] + bv0; y0[1] = acc[m][n][1] + bv0;
            y1[0] = acc[m][n][2] + bv1; y1[1] = acc[m][n][3] + bv1;
        }
    }
}

// ---------------- per-channel BN stats: one block per channel ---------------
__global__ __launch_bounds__(256) void bn_stats(const float* __restrict__ src,
                                                float* __restrict__ st)
{
    const int c = blockIdx.x;
    float s = 0.f, s2 = 0.f;
    for (int i = threadIdx.x; i < BN*HWn; i += 256) {
        const int b = i >> 12, pix = i & 4095;
        const float v = src[(((size_t)b*C + c) << 12) + pix];
        s += v; s2 += v*v;
    }
    __shared__ float sh[512];
    sh[threadIdx.x] = s; sh[256 + threadIdx.x] = s2;
    __syncthreads();
    for (int o = 128; o > 0; o >>= 1) {
        if (threadIdx.x < o) {
            sh[threadIdx.x]       += sh[threadIdx.x + o];
            sh[256 + threadIdx.x] += sh[256 + threadIdx.x + o];
        }
        __syncthreads();
    }
    if (threadIdx.x == 0) {
        const float m   = sh[0]   * (1.f/32768.f);
        const float var = sh[256] * (1.f/32768.f) - m*m;
        st[c]       = m;
        st[256 + c] = rsqrtf(var + 1e-5f);
    }
}

// ---------------- in-place BN + ReLU (for out1) ------------------------------
__global__ __launch_bounds__(256) void bn_relu(float* __restrict__ y,
    const float* __restrict__ st, const float* __restrict__ g, const float* __restrict__ bt)
{
    const int i = blockIdx.x * 256 + threadIdx.x;
    const int c = (i >> 12) & 255;
    const float v = (y[i] - st[c]) * st[256 + c] * g[c] + bt[c];
    y[i] = fmaxf(v, 0.f);
}

// ---------------- offmod partial: 27-ch conv over a 64-ci chunk --------------
__global__ __launch_bounds__(256) void conv_offmod_part(
    const float* __restrict__ src,
    const float* __restrict__ w_off, const float* __restrict__ w_mod,
    float* __restrict__ poff)
{
    __shared__ float xs[8][18][20];
    __shared__ float ws[27][8][9];
    const int tile = blockIdx.x;
    const int cb   = blockIdx.y * 64;       // ci chunk base
    const int b    = blockIdx.z;
    const int th0  = (tile >> 2) * 16;
    const int tw0  = (tile & 3) * 16;
    const int tid  = threadIdx.x;
    const int ph   = tid >> 4;
    const int pw   = tid & 15;

    float acc[27];
    #pragma unroll
    for (int o = 0; o < 27; o++) acc[o] = 0.f;

    for (int c0 = cb; c0 < cb + 64; c0 += 8) {
        for (int i = tid; i < 8*18*18; i += 256) {
            int ci = i / 324; int r = i - ci*324; int yy = r / 18; int xx = r - yy*18;
            int gy = th0 + yy - 1, gx = tw0 + xx - 1;
            float v = 0.f;
            if (gy >= 0 && gy < HH && gx >= 0 && gx < WW)
                v = src[(((size_t)b*C + c0+ci) << 12) + (gy << 6) + gx];
            xs[ci][yy][xx] = v;
        }
        for (int i = tid; i < 27*72; i += 256) {
            int o = i / 72; int r = i - o*72; int ci = r / 9; int t = r - ci*9;
            ws[o][ci][t] = (o < 18) ? w_off[(o*C + c0+ci)*9 + t]
                                    : w_mod[((o-18)*C + c0+ci)*9 + t];
        }
        __syncthreads();
        for (int ci = 0; ci < 8; ci++) {
            #pragma unroll
            for (int t = 0; t < 9; t++) {
                const float xv = xs[ci][ph + t/3][pw + t%3];
                #pragma unroll
                for (int o = 0; o < 27; o++)
                    acc[o] = fmaf(xv, ws[o][ci][t], acc[o]);
            }
        }
        __syncthreads();
    }
    const int pix = (th0+ph)*WW + tw0+pw;
    float* outp = poff + ((size_t)(blockIdx.y*BN + b)*27)*HWn;
    #pragma unroll
    for (int o = 0; o < 27; o++)
        outp[o*HWn + pix] = acc[o];
}

// ---------------- offmod combine: sum 4 partials, bias, sigmoid --------------
__global__ __launch_bounds__(256) void offmod_combine(
    const float* __restrict__ poff,
    const float* __restrict__ b_off, const float* __restrict__ b_mod,
    float* __restrict__ off, float* __restrict__ msk)
{
    const int i = blockIdx.x * 256 + threadIdx.x;   // over BN*27*HWn
    const int pix = i & 4095;
    const int r = i >> 12;
    const int b = r / 27, o = r - b*27;
    float s = 0.f;
    #pragma unroll
    for (int c = 0; c < 4; c++)
        s += poff[((size_t)(c*BN + b)*27 + o)*HWn + pix];
    if (o < 18) {
        off[((size_t)b*18 + o)*HWn + pix] = s + b_off[o];
    } else {
        const float v = s + b_mod[o-18];
        msk[((size_t)b*9 + (o-18))*HWn + pix] = 2.f / (1.f + expf(-v));
    }
}

// ---------------- deformable bilinear gather -> im2col ----------------------
__global__ __launch_bounds__(256) void deform_sample(
    const float* __restrict__ src, const float* __restrict__ off,
    const float* __restrict__ msk, float* __restrict__ col)
{
    const int pix = blockIdx.x * 256 + threadIdx.x;
    const int p   = blockIdx.y;
    const int b   = blockIdx.z;
    const int ho  = pix >> 6, wo = pix & 63;

    const float dy = off[((size_t)b*18 + 2*p    )*HWn + pix];
    const float dx = off[((size_t)b*18 + 2*p + 1)*HWn + pix];
    const float m  = msk[((size_t)b*9 + p)*HWn + pix];
    const float py = (float)(ho - 1 + p/3) + dy;
    const float px = (float)(wo - 1 + p%3) + dx;

    const float y0f = floorf(py), x0f = floorf(px);
    const float ly = py - y0f, lx = px - x0f;
    const int y0 = (int)y0f, x0 = (int)x0f;
    const int y1 = y0 + 1,  x1 = x0 + 1;
    float w00 = (1.f-ly)*(1.f-lx), w01 = (1.f-ly)*lx, w10 = ly*(1.f-lx), w11 = ly*lx;
    const bool vy0 = (y0 >= 0) && (y0 < HH), vy1 = (y1 >= 0) && (y1 < HH);
    const bool vx0 = (x0 >= 0) && (x0 < WW), vx1 = (x1 >= 0) && (x1 < WW);
    if (!(vy0 && vx0)) w00 = 0.f;
    if (!(vy0 && vx1)) w01 = 0.f;
    if (!(vy1 && vx0)) w10 = 0.f;
    if (!(vy1 && vx1)) w11 = 0.f;
    const int yc0 = min(max(y0, 0), HH-1), yc1 = min(max(y1, 0), HH-1);
    const int xc0 = min(max(x0, 0), WW-1), xc1 = min(max(x1, 0), WW-1);
    const int o00 = yc0*WW + xc0, o01 = yc0*WW + xc1;
    const int o10 = yc1*WW + xc0, o11 = yc1*WW + xc1;
    w00 *= m; w01 *= m; w10 *= m; w11 *= m;

    const float* bp = src + (size_t)b*C*HWn;
    float* cp = col + ((size_t)b*C*KT + p)*HWn + pix;
    for (int ci = 0; ci < C; ci++) {
        const float* pl = bp + ci*HWn;
        const float v = w00*pl[o00] + w01*pl[o01] + w10*pl[o10] + w11*pl[o11];
        cp[(size_t)ci*KT*HWn] = v;
    }
}

// ---------------- final: relu( bn2(d2) + bn3(res) ) -------------------------
__global__ __launch_bounds__(256) void final_fuse(
    const float* __restrict__ d2, const float* __restrict__ res,
    const float* __restrict__ st,
    const float* __restrict__ g2, const float* __restrict__ bt2,
    const float* __restrict__ g3, const float* __restrict__ bt3,
    float* __restrict__ out)
{
    const int i = blockIdx.x * 256 + threadIdx.x;
    const int c = (i >> 12) & 255;
    const float a = (d2[i]  - st[512 + c])  * st[768 + c]  * g2[c] + bt2[c];
    const float r = (res[i] - st[1024 + c]) * st[1280 + c] * g3[c] + bt3[c];
    out[i] = fmaxf(a + r, 0.f);
}

// ---------------- launcher ---------------------------------------------------
extern "C" void kernel_launch(void* const* d_in, const int* in_sizes, int n_in,
                              void* d_out, int out_size)
{
    const float* x     = (const float*)d_in[0];
    const float* w1    = (const float*)d_in[2];
    const float* b1    = (const float*)d_in[3];
    const float* g1    = (const float*)d_in[4];
    const float* bt1   = (const float*)d_in[5];
    const float* w_off = (const float*)d_in[6];
    const float* b_off = (const float*)d_in[7];
    const float* w_mod = (const float*)d_in[8];
    const float* b_mod = (const float*)d_in[9];
    const float* w_d   = (const float*)d_in[10];
    const float* b_d   = (const float*)d_in[11];
    const float* g2    = (const float*)d_in[12];
    const float* bt2   = (const float*)d_in[13];
    const float* w_ds  = (const float*)d_in[14];
    const float* b_ds  = (const float*)d_in[15];
    const float* g3    = (const float*)d_in[16];
    const float* bt3   = (const float*)d_in[17];

    float *y1, *d2, *res, *off, *msk, *col, *st, *wt1, *wtd, *wts, *poff;
    cudaGetSymbolAddress((void**)&y1,   g_y1);
    cudaGetSymbolAddress((void**)&d2,   g_d2);
    cudaGetSymbolAddress((void**)&res,  g_res);
    cudaGetSymbolAddress((void**)&off,  g_off);
    cudaGetSymbolAddress((void**)&msk,  g_mask);
    cudaGetSymbolAddress((void**)&col,  g_col);
    cudaGetSymbolAddress((void**)&st,   g_stats);
    cudaGetSymbolAddress((void**)&wt1,  g_wt1);
    cudaGetSymbolAddress((void**)&wtd,  g_wtd);
    cudaGetSymbolAddress((void**)&wts,  g_wts);
    cudaGetSymbolAddress((void**)&poff, g_poff);

    // 0) transpose weights to k-major
    transposeW<<<(KFULL*256 + 255)/256, 256>>>(w1,   wt1, KFULL);
    transposeW<<<(KFULL*256 + 255)/256, 256>>>(w_d,  wtd, KFULL);
    transposeW<<<(C*256 + 255)/256,     256>>>(w_ds, wts, C);

    // 1) conv1 via tf32 implicit GEMM
    conv3x3_mma<<<dim3(32, 4, BN), 256>>>(x, wt1, b1, y1);
    // 2) BN1 stats + in-place BN+ReLU -> out1
    bn_stats<<<256, 256>>>(y1, st);
    bn_relu<<<BN*C*HWn/256, 256>>>(y1, st, g1, bt1);
    // 3) offsets + modulation (4-way channel split + combine)
    conv_offmod_part<<<dim3(16, 4, BN), 256>>>(y1, w_off, w_mod, poff);
    offmod_combine<<<BN*27*HWn/256, 256>>>(poff, b_off, b_mod, off, msk);
    // 4) bilinear gather -> im2col
    deform_sample<<<dim3(16, KT, BN), 256>>>(y1, off, msk, col);
    // 5) deformable conv as tf32 GEMM (K = 2304)
    gemm_tf32<<<dim3(32, 4, BN), 256>>>(wtd, col, b_d, d2, KFULL);
    // 6) 1x1 shortcut as tf32 GEMM (K = 256)
    gemm_tf32<<<dim3(32, 4, BN), 256>>>(wts, x, b_ds, res, C);
    // 7) BN2 / BN3 stats
    bn_stats<<<256, 256>>>(d2,  st + 512);
    bn_stats<<<256, 256>>>(res, st + 1024);
    // 8) fused BN2 + BN3 + add + ReLU
    final_fuse<<<BN*C*HWn/256, 256>>>(d2, res, st, g2, bt2, g3, bt3, (float*)d_out);
}